// round 12
// baseline (speedup 1.0000x reference)
#include <cuda_runtime.h>
#include <cuda_fp16.h>
#include <math.h>
#include <cstdint>

// Fixed problem shapes: B=4, S=4096, D=512, H=64
#define BATCH 4
#define SEQ   4096
#define DMODEL 512
#define DHEAD  64
#define NROWS (BATCH*SEQ)          // 16384

// Scratch (device globals; no allocations allowed).
__device__ __half g_Qh[NROWS*DHEAD];   // fp16 Q row-major [row][h]
__device__ __half g_Kh[NROWS*DHEAD];   // fp16 K row-major
__device__ __half g_Vh[NROWS*DHEAD];   // fp16 V row-major
__device__ __half g_Oh[NROWS*DHEAD];   // fp16 combined attention output
// split-K partials (z = half index)
__device__ float  g_Op[2][NROWS*DHEAD];  // unnormalized O partials
__device__ float  g_m[2][NROWS];         // running max (base-2 domain)
__device__ float  g_l[2][NROWS];         // running sum

// ===========================================================================
// Warp-level MMA helpers (portable PTX — compute_103-safe)
// ===========================================================================
__device__ __forceinline__ uint32_t smem_u32(const void* p) {
    uint32_t a;
    asm("{ .reg .u64 t; cvta.to.shared.u64 t, %1; cvt.u32.u64 %0, t; }" : "=r"(a) : "l"(p));
    return a;
}
__device__ __forceinline__ void mma16816(float* d, const uint32_t* a, const uint32_t* b) {
    asm volatile(
        "mma.sync.aligned.m16n8k16.row.col.f32.f16.f16.f32 "
        "{%0,%1,%2,%3}, {%4,%5,%6,%7}, {%8,%9}, {%0,%1,%2,%3};"
        : "+f"(d[0]), "+f"(d[1]), "+f"(d[2]), "+f"(d[3])
        : "r"(a[0]), "r"(a[1]), "r"(a[2]), "r"(a[3]), "r"(b[0]), "r"(b[1]));
}
__device__ __forceinline__ void ldsm_x4(uint32_t* r, uint32_t addr) {
    asm volatile("ldmatrix.sync.aligned.m8n8.x4.shared.b16 {%0,%1,%2,%3}, [%4];"
        : "=r"(r[0]), "=r"(r[1]), "=r"(r[2]), "=r"(r[3]) : "r"(addr));
}
__device__ __forceinline__ void ldsm_x4t(uint32_t* r, uint32_t addr) {
    asm volatile("ldmatrix.sync.aligned.m8n8.x4.trans.shared.b16 {%0,%1,%2,%3}, [%4];"
        : "=r"(r[0]), "=r"(r[1]), "=r"(r[2]), "=r"(r[3]) : "r"(addr));
}
__device__ __forceinline__ void ldsm_x2t(uint32_t* r, uint32_t addr) {
    asm volatile("ldmatrix.sync.aligned.m8n8.x2.trans.shared.b16 {%0,%1}, [%2];"
        : "=r"(r[0]), "=r"(r[1]) : "r"(addr));
}
__device__ __forceinline__ float fast_exp2(float x) {
    float r;
    asm("ex2.approx.f32 %0, %1;" : "=f"(r) : "f"(x));
    return r;
}
__device__ __forceinline__ uint4 pack8(float4 a, float4 b) {
    __half2 h0 = __floats2half2_rn(a.x, a.y);
    __half2 h1 = __floats2half2_rn(a.z, a.w);
    __half2 h2 = __floats2half2_rn(b.x, b.y);
    __half2 h3 = __floats2half2_rn(b.z, b.w);
    uint4 u;
    u.x = *(uint32_t*)&h0; u.y = *(uint32_t*)&h1;
    u.z = *(uint32_t*)&h2; u.w = *(uint32_t*)&h3;
    return u;
}

// ===========================================================================
// Kernel 1: QKV projection via mma.sync fp16 (unchanged from R9 — measured).
// ===========================================================================
__global__ __launch_bounds__(256) void qkv_kernel(
    const float* __restrict__ x,
    const float* __restrict__ Wq, const float* __restrict__ bq,
    const float* __restrict__ Wk, const float* __restrict__ bk,
    const float* __restrict__ Wv, const float* __restrict__ bv)
{
    __shared__ __align__(1024) __half Xs[128*64];
    __shared__ __align__(1024) __half Wc[64*64];

    const int tid  = threadIdx.x;
    const int lane = tid & 31;
    const int warp = tid >> 5;
    const int row0 = blockIdx.x * 128;
    const int g = blockIdx.y;
    const float* W  = (g == 0) ? Wq : (g == 1) ? Wk : Wv;
    const float* bb = (g == 0) ? bq : (g == 1) ? bk : bv;
    __half* dsth    = (g == 0) ? g_Qh : (g == 1) ? g_Kh : g_Vh;

#pragma unroll
    for (int k = 0; k < 4; k++) {
        const int cid = tid + 256 * k;
        const int r = cid >> 3, c = cid & 7;
        const float* src = &x[(size_t)(row0 + r) * DMODEL + c * 8];
        *(uint4*)&Xs[r * 64 + ((c ^ (r & 7)) * 8)] =
            pack8(*(const float4*)src, *(const float4*)(src + 4));
    }
#pragma unroll
    for (int k = 0; k < 2; k++) {
        const int cid = tid + 256 * k;
        const int r = cid >> 3, c = cid & 7;
        const float* src = &W[(size_t)r * DHEAD + c * 8];
        *(uint4*)&Wc[r * 64 + ((c ^ (r & 7)) * 8)] =
            pack8(*(const float4*)src, *(const float4*)(src + 4));
    }
    __syncthreads();

    const uint32_t xs_b = smem_u32(Xs);
    const uint32_t wc_b = smem_u32(Wc);
    const int rowl = warp * 16 + (lane & 15);
    const int hb   = lane >> 4;
    const int rl   = lane & 7;
    const uint32_t boff = (uint32_t)((lane & 15) * 128);

    float acc[8][4];
#pragma unroll
    for (int j = 0; j < 8; j++)
#pragma unroll
        for (int k = 0; k < 4; k++) acc[j][k] = 0.0f;

    for (int dc8 = 0; dc8 < 8; dc8++) {
        const bool has = (dc8 + 1) < 8;
        uint4 xpre[4], wpre[2];
        if (has) {
            const int dc = (dc8 + 1) * 64;
#pragma unroll
            for (int k = 0; k < 4; k++) {
                const int cid = tid + 256 * k;
                const int r = cid >> 3, c = cid & 7;
                const float* src = &x[(size_t)(row0 + r) * DMODEL + dc + c * 8];
                xpre[k] = pack8(*(const float4*)src, *(const float4*)(src + 4));
            }
#pragma unroll
            for (int k = 0; k < 2; k++) {
                const int cid = tid + 256 * k;
                const int r = cid >> 3, c = cid & 7;
                const float* src = &W[(size_t)(dc + r) * DHEAD + c * 8];
                wpre[k] = pack8(*(const float4*)src, *(const float4*)(src + 4));
            }
        }

        uint32_t qa[4][4];
#pragma unroll
        for (int kk = 0; kk < 4; kk++)
            ldsm_x4(qa[kk], xs_b + rowl * 128 + (((2 * kk + hb) ^ (rowl & 7)) * 16));

#pragma unroll
        for (int j = 0; j < 8; j++) {
#pragma unroll
            for (int kk = 0; kk < 4; kk++) {
                uint32_t bf[2];
                ldsm_x2t(bf, wc_b + (uint32_t)(kk * 2048) + boff + (uint32_t)(((j ^ rl) * 16)));
                mma16816(acc[j], qa[kk], bf);
            }
        }

        if (has) {
            __syncthreads();
#pragma unroll
            for (int k = 0; k < 4; k++) {
                const int cid = tid + 256 * k;
                const int r = cid >> 3, c = cid & 7;
                *(uint4*)&Xs[r * 64 + ((c ^ (r & 7)) * 8)] = xpre[k];
            }
#pragma unroll
            for (int k = 0; k < 2; k++) {
                const int cid = tid + 256 * k;
                const int r = cid >> 3, c = cid & 7;
                *(uint4*)&Wc[r * 64 + ((c ^ (r & 7)) * 8)] = wpre[k];
            }
            __syncthreads();
        }
    }

    const int r0 = row0 + warp * 16 + (lane >> 2);
    const int cb = 2 * (lane & 3);
#pragma unroll
    for (int j = 0; j < 8; j++) {
        const int c = 8 * j + cb;
        const float bx = bb[c], by = bb[c + 1];
        __half2 h0 = __floats2half2_rn(acc[j][0] + bx, acc[j][1] + by);
        __half2 h1 = __floats2half2_rn(acc[j][2] + bx, acc[j][3] + by);
        *(__half2*)&dsth[(size_t)r0 * DHEAD + c]       = h0;
        *(__half2*)&dsth[(size_t)(r0 + 8) * DHEAD + c] = h1;
    }
}

// ===========================================================================
// Kernel 2: split-K fp16 mma.sync flash attention.
// 256 blocks; each = (q-tile of 128, batch, half z). Half z covers k-tiles
// [z*(qt+1), (z+1)*(qt+1)) — both halves have qt+1 iterations (<=32).
// Balanced rank map: with ~296 resident slots, blocks bid and bid+148 share
// an SM; singles (bid 108..147) get the heaviest tiles, pairs sum ~const.
// Emits unnormalized partials (O~, m, l) for the combine kernel.
// ===========================================================================
__global__ __launch_bounds__(256, 2) void attn_kernel()
{
    __shared__ __align__(1024) __half Qs[128*64];
    __shared__ __align__(1024) __half Ks[64*64];
    __shared__ __align__(1024) __half Vs[64*64];

    const int tid  = threadIdx.x;
    const int lane = tid & 31;
    const int warp = tid >> 5;

    // rank map: heaviest ranks -> singles; pair sums ~constant
    const int bid = blockIdx.x;
    const int rank = (bid < 108) ? (40 + bid) : (bid < 148) ? (bid - 108) : (403 - bid);
    const int qt = 31 - (rank >> 3);   // 0..31
    const int sub = rank & 7;
    const int b = sub & 3;             // batch
    const int z = sub >> 2;            // key-half
    const int qbase = qt * 128;
    const int kb_lo = z * (qt + 1);
    const int kb_hi = kb_lo + (qt + 1);

    // load Q tile + first K/V tile
    const __half* Qg = g_Qh + ((size_t)b * SEQ + qbase) * DHEAD;
    for (int i = tid; i < 1024; i += 256) {
        const int r = i >> 3, c = i & 7;
        *(uint4*)&Qs[r * 64 + ((c ^ (r & 7)) * 8)] = *(const uint4*)&Qg[(size_t)r * 64 + c * 8];
    }
    {
        const __half* Kg = g_Kh + ((size_t)b * SEQ + kb_lo * 64) * DHEAD;
        const __half* Vg = g_Vh + ((size_t)b * SEQ + kb_lo * 64) * DHEAD;
        for (int i = tid; i < 512; i += 256) {
            const int r = i >> 3, c = i & 7;
            *(uint4*)&Ks[r * 64 + ((c ^ (r & 7)) * 8)] = *(const uint4*)&Kg[(size_t)r * 64 + c * 8];
            *(uint4*)&Vs[r * 64 + ((c ^ (r & 7)) * 8)] = *(const uint4*)&Vg[(size_t)r * 64 + c * 8];
        }
    }
    __syncthreads();

    const uint32_t qs_b = smem_u32(Qs);
    const uint32_t ks_b = smem_u32(Ks);
    const uint32_t vs_b = smem_u32(Vs);

    // persistent Q A-fragments
    const int q0 = warp * 16;
    uint32_t qa[4][4];
    {
        const int rowl = q0 + (lane & 15);
        const int hb = lane >> 4;
#pragma unroll
        for (int kk = 0; kk < 4; kk++)
            ldsm_x4(qa[kk], qs_b + rowl * 128 + (((2 * kk + hb) ^ (rowl & 7)) * 16));
    }

    const int rl  = lane & 7;
    const int hb8 = (lane >> 3) & 1;
    // x4 K addressing: lanes 0-15 -> keys 8j+rl, lanes 16-31 -> keys 8(j+1)+rl
    const int krow_off = ((lane & 16) >> 1) + rl;   // 0..15
    uint32_t koff2[4];
#pragma unroll
    for (int kk = 0; kk < 4; kk++)
        koff2[kk] = (uint32_t)(krow_off * 128 + (((2 * kk + hb8) ^ rl) * 16));
    // x4t V addressing: lanes 0-15 -> col j, lanes 16-31 -> col j+1
    const uint32_t voff = (uint32_t)((lane & 15) * 128);
    const int hv = lane >> 4;

    const int row0 = qbase + q0 + (lane >> 2);
    const float C = 0.015625f * 1.44269504088896f; // (1/sqrt(4096)) * log2(e)

    float m0 = -1e30f, m1 = -1e30f, l0 = 0.0f, l1 = 0.0f;
    float o[8][4];
#pragma unroll
    for (int j = 0; j < 8; j++)
#pragma unroll
        for (int k = 0; k < 4; k++) o[j][k] = 0.0f;

    for (int kb = kb_lo; kb < kb_hi; kb++) {
        // prefetch next K/V tile into registers
        const bool has = (kb + 1) < kb_hi;
        uint4 kpre[2], vpre[2];
        if (has) {
            const __half* Kg = g_Kh + ((size_t)b * SEQ + (kb + 1) * 64) * DHEAD;
            const __half* Vg = g_Vh + ((size_t)b * SEQ + (kb + 1) * 64) * DHEAD;
#pragma unroll
            for (int t = 0; t < 2; t++) {
                const int i = tid + 256 * t;
                const int r = i >> 3, c = i & 7;
                kpre[t] = *(const uint4*)&Kg[(size_t)r * 64 + c * 8];
                vpre[t] = *(const uint4*)&Vg[(size_t)r * 64 + c * 8];
            }
        }

        // ---- S = Q * K^T (x4 ldsm: two j per load) ----
        float s[8][4];
#pragma unroll
        for (int j = 0; j < 8; j++)
#pragma unroll
            for (int k = 0; k < 4; k++) s[j][k] = 0.0f;

#pragma unroll
        for (int j = 0; j < 8; j += 2) {
#pragma unroll
            for (int kk = 0; kk < 4; kk++) {
                uint32_t bf[4];
                ldsm_x4(bf, ks_b + (uint32_t)(j * 1024) + koff2[kk]);
                mma16816(s[j],     qa[kk], bf);
                mma16816(s[j + 1], qa[kk], bf + 2);
            }
        }

        // ---- scale (+ causal mask on diagonal tiles) ----
#pragma unroll
        for (int j = 0; j < 8; j++)
#pragma unroll
            for (int k = 0; k < 4; k++) s[j][k] *= C;

        if (kb * 64 + 63 > qbase + q0) {
#pragma unroll
            for (int j = 0; j < 8; j++) {
                const int kc = kb * 64 + 8 * j + 2 * (lane & 3);
                if (kc     > row0)     s[j][0] = -1e30f;
                if (kc + 1 > row0)     s[j][1] = -1e30f;
                if (kc     > row0 + 8) s[j][2] = -1e30f;
                if (kc + 1 > row0 + 8) s[j][3] = -1e30f;
            }
        }

        // ---- online softmax ----
        float mx0 = -1e30f, mx1 = -1e30f;
#pragma unroll
        for (int j = 0; j < 8; j++) {
            mx0 = fmaxf(mx0, fmaxf(s[j][0], s[j][1]));
            mx1 = fmaxf(mx1, fmaxf(s[j][2], s[j][3]));
        }
        mx0 = fmaxf(mx0, __shfl_xor_sync(0xffffffffu, mx0, 1, 4));
        mx0 = fmaxf(mx0, __shfl_xor_sync(0xffffffffu, mx0, 2, 4));
        mx1 = fmaxf(mx1, __shfl_xor_sync(0xffffffffu, mx1, 1, 4));
        mx1 = fmaxf(mx1, __shfl_xor_sync(0xffffffffu, mx1, 2, 4));

        const float mn0 = fmaxf(m0, mx0);
        const float mn1 = fmaxf(m1, mx1);
        const float c0 = fast_exp2(m0 - mn0);
        const float c1 = fast_exp2(m1 - mn1);
        m0 = mn0; m1 = mn1;

        uint32_t pa[4][4];
        float sum0 = 0.0f, sum1 = 0.0f;
#pragma unroll
        for (int j = 0; j < 8; j++) {
            const float p0 = fast_exp2(s[j][0] - mn0);
            const float p1 = fast_exp2(s[j][1] - mn0);
            const float p2 = fast_exp2(s[j][2] - mn1);
            const float p3 = fast_exp2(s[j][3] - mn1);
            sum0 += p0 + p1;
            sum1 += p2 + p3;
            const __half2 h01 = __floats2half2_rn(p0, p1);
            const __half2 h23 = __floats2half2_rn(p2, p3);
            const int kk = j >> 1, hi = (j & 1) << 1;
            pa[kk][hi]     = *(const uint32_t*)&h01;
            pa[kk][hi + 1] = *(const uint32_t*)&h23;
        }
        sum0 += __shfl_xor_sync(0xffffffffu, sum0, 1, 4);
        sum0 += __shfl_xor_sync(0xffffffffu, sum0, 2, 4);
        sum1 += __shfl_xor_sync(0xffffffffu, sum1, 1, 4);
        sum1 += __shfl_xor_sync(0xffffffffu, sum1, 2, 4);
        l0 = l0 * c0 + sum0;
        l1 = l1 * c1 + sum1;

#pragma unroll
        for (int j = 0; j < 8; j++) {
            o[j][0] *= c0; o[j][1] *= c0;
            o[j][2] *= c1; o[j][3] *= c1;
        }

        // ---- O += P * V (x4 trans ldsm: two j per load) ----
#pragma unroll
        for (int kk = 0; kk < 4; kk++) {
#pragma unroll
            for (int j = 0; j < 8; j += 2) {
                uint32_t vb[4];
                ldsm_x4t(vb, vs_b + (uint32_t)(kk * 2048) + voff
                             + (uint32_t)((((j + hv) ^ rl) * 16)));
                mma16816(o[j],     pa[kk], vb);
                mma16816(o[j + 1], pa[kk], vb + 2);
            }
        }

        if (has) {
            __syncthreads();
#pragma unroll
            for (int t = 0; t < 2; t++) {
                const int i = tid + 256 * t;
                const int r = i >> 3, c = i & 7;
                *(uint4*)&Ks[r * 64 + ((c ^ (r & 7)) * 8)] = kpre[t];
                *(uint4*)&Vs[r * 64 + ((c ^ (r & 7)) * 8)] = vpre[t];
            }
            __syncthreads();
        }
    }

    // ---- epilogue: unnormalized partials (fp32) + m/l ----
    float* Op0 = &g_Op[z][((size_t)b * SEQ + row0) * DHEAD];
    float* Op1 = Op0 + 8 * DHEAD;
    const int cbase = 2 * (lane & 3);
#pragma unroll
    for (int j = 0; j < 8; j++) {
        *(float2*)&Op0[8 * j + cbase] = make_float2(o[j][0], o[j][1]);
        *(float2*)&Op1[8 * j + cbase] = make_float2(o[j][2], o[j][3]);
    }
    if ((lane & 3) == 0) {
        const size_t gr = (size_t)b * SEQ + row0;
        g_m[z][gr] = m0;  g_l[z][gr] = l0;
        g_m[z][gr + 8] = m1;  g_l[z][gr + 8] = l1;
    }
}

// ===========================================================================
// Kernel 2b: combine the two split-K halves -> fp16 g_Oh.
// One warp per row; lane covers 2 head dims.
// ===========================================================================
__global__ __launch_bounds__(256) void combine_kernel()
{
    const int tid  = threadIdx.x;
    const int lane = tid & 31;
    const int warp = tid >> 5;
    const int row  = blockIdx.x * 8 + warp;

    const float m0 = g_m[0][row], m1 = g_m[1][row];
    const float l0 = g_l[0][row], l1 = g_l[1][row];
    const float mm = fmaxf(m0, m1);
    const float a0 = fast_exp2(m0 - mm);
    const float a1 = fast_exp2(m1 - mm);
    const float inv = 1.0f / (l0 * a0 + l1 * a1);
    const float w0 = a0 * inv, w1 = a1 * inv;

    const float2 v0 = *(const float2*)&g_Op[0][(size_t)row * DHEAD + 2 * lane];
    const float2 v1 = *(const float2*)&g_Op[1][(size_t)row * DHEAD + 2 * lane];
    __half2 h = __floats2half2_rn(v0.x * w0 + v1.x * w1, v0.y * w0 + v1.y * w1);
    *(__half2*)&g_Oh[(size_t)row * DHEAD + 2 * lane] = h;
}

// ===========================================================================
// Kernel 3: output projection via mma.sync fp16 (unchanged from R9).
// ===========================================================================
__global__ __launch_bounds__(256) void proj_kernel(
    const float* __restrict__ Wo, const float* __restrict__ bo,
    float* __restrict__ out)
{
    __shared__ __align__(1024) __half Os[128*64];
    __shared__ __align__(1024) __half Wc0[64*64];
    __shared__ __align__(1024) __half Wc1[64*64];

    const int tid  = threadIdx.x;
    const int lane = tid & 31;
    const int warp = tid >> 5;
    const int row0 = blockIdx.x * 128;
    const int c0   = blockIdx.y * 128;

    for (int i = tid; i < 1024; i += 256) {
        const int r = i >> 3, c = i & 7;
        *(uint4*)&Os[r * 64 + ((c ^ (r & 7)) * 8)] =
            *(const uint4*)&g_Oh[(size_t)(row0 + r) * DHEAD + c * 8];
    }
    for (int i = tid; i < 1024; i += 256) {
        const int h = i >> 4, c = i & 15;
        const float* src = &Wo[(size_t)h * DMODEL + c0 + c * 8];
        uint4 u = pack8(*(const float4*)src, *(const float4*)(src + 4));
        __half* dst = (c < 8) ? Wc0 : Wc1;
        const int cc = c & 7;
        *(uint4*)&dst[h * 64 + ((cc ^ (h & 7)) * 8)] = u;
    }
    __syncthreads();

    const uint32_t os_b  = smem_u32(Os);
    const uint32_t wc0_b = smem_u32(Wc0);
    const uint32_t wc1_b = smem_u32(Wc1);

    const int rowl = warp * 16 + (lane & 15);
    const int hb = lane >> 4;
    uint32_t qa[4][4];
#pragma unroll
    for (int kk = 0; kk < 4; kk++)
        ldsm_x4(qa[kk], os_b + rowl * 128 + (((2 * kk + hb) ^ (rowl & 7)) * 16));

    const int rl = lane & 7;
    const uint32_t boff = (uint32_t)((lane & 15) * 128);

    float acc[16][4];
#pragma unroll
    for (int j = 0; j < 16; j++)
#pragma unroll
        for (int k = 0; k < 4; k++) acc[j][k] = 0.0f;

#pragma unroll
    for (int j = 0; j < 16; j++) {
        const uint32_t base = (j < 8) ? wc0_b : wc1_b;
        const int jj = j & 7;
#pragma unroll
        for (int kk = 0; kk < 4; kk++) {
            uint32_t bf[2];
            ldsm_x2t(bf, base + (uint32_t)(kk * 2048) + boff + (uint32_t)(((jj ^ rl) * 16)));
            mma16816(acc[j], qa[kk], bf);
        }
    }

    const int r0 = row0 + warp * 16 + (lane >> 2);
    const int cb = 2 * (lane & 3);
#pragma unroll
    for (int j = 0; j < 16; j++) {
        const int c = c0 + 8 * j + cb;
        const float bx = bo[c], by = bo[c + 1];
        float2 w0 = make_float2(acc[j][0] + bx, acc[j][1] + by);
        float2 w1 = make_float2(acc[j][2] + bx, acc[j][3] + by);
        *(float2*)&out[(size_t)r0 * DMODEL + c]       = w0;
        *(float2*)&out[(size_t)(r0 + 8) * DMODEL + c] = w1;
    }
}

// ---------------------------------------------------------------------------
extern "C" void kernel_launch(void* const* d_in, const int* in_sizes, int n_in,
                              void* d_out, int out_size)
{
    const float* x  = (const float*)d_in[0];
    const float* Wq = (const float*)d_in[1];
    const float* bq = (const float*)d_in[2];
    const float* Wk = (const float*)d_in[3];
    const float* bk = (const float*)d_in[4];
    const float* Wv = (const float*)d_in[5];
    const float* bv = (const float*)d_in[6];
    const float* Wo = (const float*)d_in[7];
    const float* bo = (const float*)d_in[8];
    float* out = (float*)d_out;

    qkv_kernel<<<dim3(NROWS / 128, 3), 256>>>(x, Wq, bq, Wk, bk, Wv, bv);
    attn_kernel<<<256, 256>>>();
    combine_kernel<<<NROWS / 8, 256>>>();
    proj_kernel<<<dim3(NROWS / 128, DMODEL / 128), 256>>>(Wo, bo, out);
}

// round 13
// speedup vs baseline: 1.5461x; 1.5461x over previous
#include <cuda_runtime.h>
#include <cuda_fp16.h>
#include <math.h>
#include <cstdint>

// Fixed problem shapes: B=4, S=4096, D=512, H=64
#define BATCH 4
#define SEQ   4096
#define DMODEL 512
#define DHEAD  64
#define NROWS (BATCH*SEQ)          // 16384

// Scratch (device globals; no allocations allowed).
__device__ __half g_Qh[NROWS*DHEAD];   // fp16 Q row-major [row][h]
__device__ __half g_Kh[NROWS*DHEAD];   // fp16 K row-major
__device__ __half g_Vh[NROWS*DHEAD];   // fp16 V row-major
__device__ __half g_Oh[NROWS*DHEAD];   // fp16 combined attention output
// split-K partials (z = half index)
__device__ float  g_Op[2][NROWS*DHEAD];  // unnormalized O partials
__device__ float  g_m[2][NROWS];         // running max (base-2 domain)
__device__ float  g_l[2][NROWS];         // running sum

// ===========================================================================
// Warp-level MMA helpers (portable PTX — compute_103-safe)
// ===========================================================================
__device__ __forceinline__ uint32_t smem_u32(const void* p) {
    uint32_t a;
    asm("{ .reg .u64 t; cvta.to.shared.u64 t, %1; cvt.u32.u64 %0, t; }" : "=r"(a) : "l"(p));
    return a;
}
__device__ __forceinline__ void mma16816(float* d, const uint32_t* a, const uint32_t* b) {
    asm volatile(
        "mma.sync.aligned.m16n8k16.row.col.f32.f16.f16.f32 "
        "{%0,%1,%2,%3}, {%4,%5,%6,%7}, {%8,%9}, {%0,%1,%2,%3};"
        : "+f"(d[0]), "+f"(d[1]), "+f"(d[2]), "+f"(d[3])
        : "r"(a[0]), "r"(a[1]), "r"(a[2]), "r"(a[3]), "r"(b[0]), "r"(b[1]));
}
__device__ __forceinline__ void ldsm_x4(uint32_t* r, uint32_t addr) {
    asm volatile("ldmatrix.sync.aligned.m8n8.x4.shared.b16 {%0,%1,%2,%3}, [%4];"
        : "=r"(r[0]), "=r"(r[1]), "=r"(r[2]), "=r"(r[3]) : "r"(addr));
}
__device__ __forceinline__ void ldsm_x4t(uint32_t* r, uint32_t addr) {
    asm volatile("ldmatrix.sync.aligned.m8n8.x4.trans.shared.b16 {%0,%1,%2,%3}, [%4];"
        : "=r"(r[0]), "=r"(r[1]), "=r"(r[2]), "=r"(r[3]) : "r"(addr));
}
__device__ __forceinline__ void ldsm_x2t(uint32_t* r, uint32_t addr) {
    asm volatile("ldmatrix.sync.aligned.m8n8.x2.trans.shared.b16 {%0,%1}, [%2];"
        : "=r"(r[0]), "=r"(r[1]) : "r"(addr));
}
__device__ __forceinline__ float fast_exp2(float x) {
    float r;
    asm("ex2.approx.f32 %0, %1;" : "=f"(r) : "f"(x));
    return r;
}
__device__ __forceinline__ uint4 pack8(float4 a, float4 b) {
    __half2 h0 = __floats2half2_rn(a.x, a.y);
    __half2 h1 = __floats2half2_rn(a.z, a.w);
    __half2 h2 = __floats2half2_rn(b.x, b.y);
    __half2 h3 = __floats2half2_rn(b.z, b.w);
    uint4 u;
    u.x = *(uint32_t*)&h0; u.y = *(uint32_t*)&h1;
    u.z = *(uint32_t*)&h2; u.w = *(uint32_t*)&h3;
    return u;
}

// ===========================================================================
// Kernel 1: QKV projection via mma.sync fp16 (unchanged — measured 38 µs).
// ===========================================================================
__global__ __launch_bounds__(256) void qkv_kernel(
    const float* __restrict__ x,
    const float* __restrict__ Wq, const float* __restrict__ bq,
    const float* __restrict__ Wk, const float* __restrict__ bk,
    const float* __restrict__ Wv, const float* __restrict__ bv)
{
    __shared__ __align__(1024) __half Xs[128*64];
    __shared__ __align__(1024) __half Wc[64*64];

    const int tid  = threadIdx.x;
    const int lane = tid & 31;
    const int warp = tid >> 5;
    const int row0 = blockIdx.x * 128;
    const int g = blockIdx.y;
    const float* W  = (g == 0) ? Wq : (g == 1) ? Wk : Wv;
    const float* bb = (g == 0) ? bq : (g == 1) ? bk : bv;
    __half* dsth    = (g == 0) ? g_Qh : (g == 1) ? g_Kh : g_Vh;

#pragma unroll
    for (int k = 0; k < 4; k++) {
        const int cid = tid + 256 * k;
        const int r = cid >> 3, c = cid & 7;
        const float* src = &x[(size_t)(row0 + r) * DMODEL + c * 8];
        *(uint4*)&Xs[r * 64 + ((c ^ (r & 7)) * 8)] =
            pack8(*(const float4*)src, *(const float4*)(src + 4));
    }
#pragma unroll
    for (int k = 0; k < 2; k++) {
        const int cid = tid + 256 * k;
        const int r = cid >> 3, c = cid & 7;
        const float* src = &W[(size_t)r * DHEAD + c * 8];
        *(uint4*)&Wc[r * 64 + ((c ^ (r & 7)) * 8)] =
            pack8(*(const float4*)src, *(const float4*)(src + 4));
    }
    __syncthreads();

    const uint32_t xs_b = smem_u32(Xs);
    const uint32_t wc_b = smem_u32(Wc);
    const int rowl = warp * 16 + (lane & 15);
    const int hb   = lane >> 4;
    const int rl   = lane & 7;
    const uint32_t boff = (uint32_t)((lane & 15) * 128);

    float acc[8][4];
#pragma unroll
    for (int j = 0; j < 8; j++)
#pragma unroll
        for (int k = 0; k < 4; k++) acc[j][k] = 0.0f;

    for (int dc8 = 0; dc8 < 8; dc8++) {
        const bool has = (dc8 + 1) < 8;
        uint4 xpre[4], wpre[2];
        if (has) {
            const int dc = (dc8 + 1) * 64;
#pragma unroll
            for (int k = 0; k < 4; k++) {
                const int cid = tid + 256 * k;
                const int r = cid >> 3, c = cid & 7;
                const float* src = &x[(size_t)(row0 + r) * DMODEL + dc + c * 8];
                xpre[k] = pack8(*(const float4*)src, *(const float4*)(src + 4));
            }
#pragma unroll
            for (int k = 0; k < 2; k++) {
                const int cid = tid + 256 * k;
                const int r = cid >> 3, c = cid & 7;
                const float* src = &W[(size_t)(dc + r) * DHEAD + c * 8];
                wpre[k] = pack8(*(const float4*)src, *(const float4*)(src + 4));
            }
        }

        uint32_t qa[4][4];
#pragma unroll
        for (int kk = 0; kk < 4; kk++)
            ldsm_x4(qa[kk], xs_b + rowl * 128 + (((2 * kk + hb) ^ (rowl & 7)) * 16));

#pragma unroll
        for (int j = 0; j < 8; j++) {
#pragma unroll
            for (int kk = 0; kk < 4; kk++) {
                uint32_t bf[2];
                ldsm_x2t(bf, wc_b + (uint32_t)(kk * 2048) + boff + (uint32_t)(((j ^ rl) * 16)));
                mma16816(acc[j], qa[kk], bf);
            }
        }

        if (has) {
            __syncthreads();
#pragma unroll
            for (int k = 0; k < 4; k++) {
                const int cid = tid + 256 * k;
                const int r = cid >> 3, c = cid & 7;
                *(uint4*)&Xs[r * 64 + ((c ^ (r & 7)) * 8)] = xpre[k];
            }
#pragma unroll
            for (int k = 0; k < 2; k++) {
                const int cid = tid + 256 * k;
                const int r = cid >> 3, c = cid & 7;
                *(uint4*)&Wc[r * 64 + ((c ^ (r & 7)) * 8)] = wpre[k];
            }
            __syncthreads();
        }
    }

    const int r0 = row0 + warp * 16 + (lane >> 2);
    const int cb = 2 * (lane & 3);
#pragma unroll
    for (int j = 0; j < 8; j++) {
        const int c = 8 * j + cb;
        const float bx = bb[c], by = bb[c + 1];
        __half2 h0 = __floats2half2_rn(acc[j][0] + bx, acc[j][1] + by);
        __half2 h1 = __floats2half2_rn(acc[j][2] + bx, acc[j][3] + by);
        *(__half2*)&dsth[(size_t)r0 * DHEAD + c]       = h0;
        *(__half2*)&dsth[(size_t)(r0 + 8) * DHEAD + c] = h1;
    }
}

// ===========================================================================
// Kernel 2: split-K fp16 mma.sync flash attention.
// NOTE: occupancy hint deliberately ABSENT — __launch_bounds__(256, 2) in R12
// capped regs at 128 and spilled the mainloop (the R12 regression).
// 256 blocks; each = (q-tile of 128, batch, half z). Half z covers k-tiles
// [z*(qt+1), (z+1)*(qt+1)) — both halves have qt+1 iterations (<=32).
// Rank map: wave 1 = ranks 0..147 (heavy+mid); wave-2 lightest blocks backfill.
// Emits unnormalized partials (O~, m, l) for the combine kernel.
// ===========================================================================
__global__ __launch_bounds__(256) void attn_kernel()
{
    __shared__ __align__(1024) __half Qs[128*64];
    __shared__ __align__(1024) __half Ks[64*64];
    __shared__ __align__(1024) __half Vs[64*64];

    const int tid  = threadIdx.x;
    const int lane = tid & 31;
    const int warp = tid >> 5;

    // rank map: heaviest ranks -> singles; pair sums ~constant
    const int bid = blockIdx.x;
    const int rank = (bid < 108) ? (40 + bid) : (bid < 148) ? (bid - 108) : (403 - bid);
    const int qt = 31 - (rank >> 3);   // 0..31
    const int sub = rank & 7;
    const int b = sub & 3;             // batch
    const int z = sub >> 2;            // key-half
    const int qbase = qt * 128;
    const int kb_lo = z * (qt + 1);
    const int kb_hi = kb_lo + (qt + 1);

    // load Q tile + first K/V tile
    const __half* Qg = g_Qh + ((size_t)b * SEQ + qbase) * DHEAD;
    for (int i = tid; i < 1024; i += 256) {
        const int r = i >> 3, c = i & 7;
        *(uint4*)&Qs[r * 64 + ((c ^ (r & 7)) * 8)] = *(const uint4*)&Qg[(size_t)r * 64 + c * 8];
    }
    {
        const __half* Kg = g_Kh + ((size_t)b * SEQ + kb_lo * 64) * DHEAD;
        const __half* Vg = g_Vh + ((size_t)b * SEQ + kb_lo * 64) * DHEAD;
        for (int i = tid; i < 512; i += 256) {
            const int r = i >> 3, c = i & 7;
            *(uint4*)&Ks[r * 64 + ((c ^ (r & 7)) * 8)] = *(const uint4*)&Kg[(size_t)r * 64 + c * 8];
            *(uint4*)&Vs[r * 64 + ((c ^ (r & 7)) * 8)] = *(const uint4*)&Vg[(size_t)r * 64 + c * 8];
        }
    }
    __syncthreads();

    const uint32_t qs_b = smem_u32(Qs);
    const uint32_t ks_b = smem_u32(Ks);
    const uint32_t vs_b = smem_u32(Vs);

    // persistent Q A-fragments
    const int q0 = warp * 16;
    uint32_t qa[4][4];
    {
        const int rowl = q0 + (lane & 15);
        const int hb = lane >> 4;
#pragma unroll
        for (int kk = 0; kk < 4; kk++)
            ldsm_x4(qa[kk], qs_b + rowl * 128 + (((2 * kk + hb) ^ (rowl & 7)) * 16));
    }

    const int rl  = lane & 7;
    const int hb8 = (lane >> 3) & 1;
    // x4 K addressing: lanes 0-15 -> keys 8j+rl, lanes 16-31 -> keys 8(j+1)+rl
    const int krow_off = ((lane & 16) >> 1) + rl;   // 0..15
    uint32_t koff2[4];
#pragma unroll
    for (int kk = 0; kk < 4; kk++)
        koff2[kk] = (uint32_t)(krow_off * 128 + (((2 * kk + hb8) ^ rl) * 16));
    // x4t V addressing: lanes 0-15 -> col j, lanes 16-31 -> col j+1
    const uint32_t voff = (uint32_t)((lane & 15) * 128);
    const int hv = lane >> 4;

    const int row0 = qbase + q0 + (lane >> 2);
    const float C = 0.015625f * 1.44269504088896f; // (1/sqrt(4096)) * log2(e)

    float m0 = -1e30f, m1 = -1e30f, l0 = 0.0f, l1 = 0.0f;
    float o[8][4];
#pragma unroll
    for (int j = 0; j < 8; j++)
#pragma unroll
        for (int k = 0; k < 4; k++) o[j][k] = 0.0f;

    for (int kb = kb_lo; kb < kb_hi; kb++) {
        // prefetch next K/V tile into registers
        const bool has = (kb + 1) < kb_hi;
        uint4 kpre[2], vpre[2];
        if (has) {
            const __half* Kg = g_Kh + ((size_t)b * SEQ + (kb + 1) * 64) * DHEAD;
            const __half* Vg = g_Vh + ((size_t)b * SEQ + (kb + 1) * 64) * DHEAD;
#pragma unroll
            for (int t = 0; t < 2; t++) {
                const int i = tid + 256 * t;
                const int r = i >> 3, c = i & 7;
                kpre[t] = *(const uint4*)&Kg[(size_t)r * 64 + c * 8];
                vpre[t] = *(const uint4*)&Vg[(size_t)r * 64 + c * 8];
            }
        }

        // ---- S = Q * K^T (x4 ldsm: two j per load) ----
        float s[8][4];
#pragma unroll
        for (int j = 0; j < 8; j++)
#pragma unroll
            for (int k = 0; k < 4; k++) s[j][k] = 0.0f;

#pragma unroll
        for (int j = 0; j < 8; j += 2) {
#pragma unroll
            for (int kk = 0; kk < 4; kk++) {
                uint32_t bf[4];
                ldsm_x4(bf, ks_b + (uint32_t)(j * 1024) + koff2[kk]);
                mma16816(s[j],     qa[kk], bf);
                mma16816(s[j + 1], qa[kk], bf + 2);
            }
        }

        // ---- scale (+ causal mask on diagonal tiles) ----
#pragma unroll
        for (int j = 0; j < 8; j++)
#pragma unroll
            for (int k = 0; k < 4; k++) s[j][k] *= C;

        if (kb * 64 + 63 > qbase + q0) {
#pragma unroll
            for (int j = 0; j < 8; j++) {
                const int kc = kb * 64 + 8 * j + 2 * (lane & 3);
                if (kc     > row0)     s[j][0] = -1e30f;
                if (kc + 1 > row0)     s[j][1] = -1e30f;
                if (kc     > row0 + 8) s[j][2] = -1e30f;
                if (kc + 1 > row0 + 8) s[j][3] = -1e30f;
            }
        }

        // ---- online softmax ----
        float mx0 = -1e30f, mx1 = -1e30f;
#pragma unroll
        for (int j = 0; j < 8; j++) {
            mx0 = fmaxf(mx0, fmaxf(s[j][0], s[j][1]));
            mx1 = fmaxf(mx1, fmaxf(s[j][2], s[j][3]));
        }
        mx0 = fmaxf(mx0, __shfl_xor_sync(0xffffffffu, mx0, 1, 4));
        mx0 = fmaxf(mx0, __shfl_xor_sync(0xffffffffu, mx0, 2, 4));
        mx1 = fmaxf(mx1, __shfl_xor_sync(0xffffffffu, mx1, 1, 4));
        mx1 = fmaxf(mx1, __shfl_xor_sync(0xffffffffu, mx1, 2, 4));

        const float mn0 = fmaxf(m0, mx0);
        const float mn1 = fmaxf(m1, mx1);
        const float c0 = fast_exp2(m0 - mn0);
        const float c1 = fast_exp2(m1 - mn1);
        m0 = mn0; m1 = mn1;

        uint32_t pa[4][4];
        float sum0 = 0.0f, sum1 = 0.0f;
#pragma unroll
        for (int j = 0; j < 8; j++) {
            const float p0 = fast_exp2(s[j][0] - mn0);
            const float p1 = fast_exp2(s[j][1] - mn0);
            const float p2 = fast_exp2(s[j][2] - mn1);
            const float p3 = fast_exp2(s[j][3] - mn1);
            sum0 += p0 + p1;
            sum1 += p2 + p3;
            const __half2 h01 = __floats2half2_rn(p0, p1);
            const __half2 h23 = __floats2half2_rn(p2, p3);
            const int kk = j >> 1, hi = (j & 1) << 1;
            pa[kk][hi]     = *(const uint32_t*)&h01;
            pa[kk][hi + 1] = *(const uint32_t*)&h23;
        }
        sum0 += __shfl_xor_sync(0xffffffffu, sum0, 1, 4);
        sum0 += __shfl_xor_sync(0xffffffffu, sum0, 2, 4);
        sum1 += __shfl_xor_sync(0xffffffffu, sum1, 1, 4);
        sum1 += __shfl_xor_sync(0xffffffffu, sum1, 2, 4);
        l0 = l0 * c0 + sum0;
        l1 = l1 * c1 + sum1;

#pragma unroll
        for (int j = 0; j < 8; j++) {
            o[j][0] *= c0; o[j][1] *= c0;
            o[j][2] *= c1; o[j][3] *= c1;
        }

        // ---- O += P * V (x4 trans ldsm: two j per load) ----
#pragma unroll
        for (int kk = 0; kk < 4; kk++) {
#pragma unroll
            for (int j = 0; j < 8; j += 2) {
                uint32_t vb[4];
                ldsm_x4t(vb, vs_b + (uint32_t)(kk * 2048) + voff
                             + (uint32_t)((((j + hv) ^ rl) * 16)));
                mma16816(o[j],     pa[kk], vb);
                mma16816(o[j + 1], pa[kk], vb + 2);
            }
        }

        if (has) {
            __syncthreads();
#pragma unroll
            for (int t = 0; t < 2; t++) {
                const int i = tid + 256 * t;
                const int r = i >> 3, c = i & 7;
                *(uint4*)&Ks[r * 64 + ((c ^ (r & 7)) * 8)] = kpre[t];
                *(uint4*)&Vs[r * 64 + ((c ^ (r & 7)) * 8)] = vpre[t];
            }
            __syncthreads();
        }
    }

    // ---- epilogue: unnormalized partials (fp32) + m/l ----
    float* Op0 = &g_Op[z][((size_t)b * SEQ + row0) * DHEAD];
    float* Op1 = Op0 + 8 * DHEAD;
    const int cbase = 2 * (lane & 3);
#pragma unroll
    for (int j = 0; j < 8; j++) {
        *(float2*)&Op0[8 * j + cbase] = make_float2(o[j][0], o[j][1]);
        *(float2*)&Op1[8 * j + cbase] = make_float2(o[j][2], o[j][3]);
    }
    if ((lane & 3) == 0) {
        const size_t gr = (size_t)b * SEQ + row0;
        g_m[z][gr] = m0;  g_l[z][gr] = l0;
        g_m[z][gr + 8] = m1;  g_l[z][gr + 8] = l1;
    }
}

// ===========================================================================
// Kernel 2b: combine the two split-K halves -> fp16 g_Oh.
// One warp per row; lane covers 2 head dims.
// ===========================================================================
__global__ __launch_bounds__(256) void combine_kernel()
{
    const int tid  = threadIdx.x;
    const int lane = tid & 31;
    const int warp = tid >> 5;
    const int row  = blockIdx.x * 8 + warp;

    const float m0 = g_m[0][row], m1 = g_m[1][row];
    const float l0 = g_l[0][row], l1 = g_l[1][row];
    const float mm = fmaxf(m0, m1);
    const float a0 = fast_exp2(m0 - mm);
    const float a1 = fast_exp2(m1 - mm);
    const float inv = 1.0f / (l0 * a0 + l1 * a1);
    const float w0 = a0 * inv, w1 = a1 * inv;

    const float2 v0 = *(const float2*)&g_Op[0][(size_t)row * DHEAD + 2 * lane];
    const float2 v1 = *(const float2*)&g_Op[1][(size_t)row * DHEAD + 2 * lane];
    __half2 h = __floats2half2_rn(v0.x * w0 + v1.x * w1, v0.y * w0 + v1.y * w1);
    *(__half2*)&g_Oh[(size_t)row * DHEAD + 2 * lane] = h;
}

// ===========================================================================
// Kernel 3: output projection via mma.sync fp16 (unchanged — measured 22 µs).
// ===========================================================================
__global__ __launch_bounds__(256) void proj_kernel(
    const float* __restrict__ Wo, const float* __restrict__ bo,
    float* __restrict__ out)
{
    __shared__ __align__(1024) __half Os[128*64];
    __shared__ __align__(1024) __half Wc0[64*64];
    __shared__ __align__(1024) __half Wc1[64*64];

    const int tid  = threadIdx.x;
    const int lane = tid & 31;
    const int warp = tid >> 5;
    const int row0 = blockIdx.x * 128;
    const int c0   = blockIdx.y * 128;

    for (int i = tid; i < 1024; i += 256) {
        const int r = i >> 3, c = i & 7;
        *(uint4*)&Os[r * 64 + ((c ^ (r & 7)) * 8)] =
            *(const uint4*)&g_Oh[(size_t)(row0 + r) * DHEAD + c * 8];
    }
    for (int i = tid; i < 1024; i += 256) {
        const int h = i >> 4, c = i & 15;
        const float* src = &Wo[(size_t)h * DMODEL + c0 + c * 8];
        uint4 u = pack8(*(const float4*)src, *(const float4*)(src + 4));
        __half* dst = (c < 8) ? Wc0 : Wc1;
        const int cc = c & 7;
        *(uint4*)&dst[h * 64 + ((cc ^ (h & 7)) * 8)] = u;
    }
    __syncthreads();

    const uint32_t os_b  = smem_u32(Os);
    const uint32_t wc0_b = smem_u32(Wc0);
    const uint32_t wc1_b = smem_u32(Wc1);

    const int rowl = warp * 16 + (lane & 15);
    const int hb = lane >> 4;
    uint32_t qa[4][4];
#pragma unroll
    for (int kk = 0; kk < 4; kk++)
        ldsm_x4(qa[kk], os_b + rowl * 128 + (((2 * kk + hb) ^ (rowl & 7)) * 16));

    const int rl = lane & 7;
    const uint32_t boff = (uint32_t)((lane & 15) * 128);

    float acc[16][4];
#pragma unroll
    for (int j = 0; j < 16; j++)
#pragma unroll
        for (int k = 0; k < 4; k++) acc[j][k] = 0.0f;

#pragma unroll
    for (int j = 0; j < 16; j++) {
        const uint32_t base = (j < 8) ? wc0_b : wc1_b;
        const int jj = j & 7;
#pragma unroll
        for (int kk = 0; kk < 4; kk++) {
            uint32_t bf[2];
            ldsm_x2t(bf, base + (uint32_t)(kk * 2048) + boff + (uint32_t)(((jj ^ rl) * 16)));
            mma16816(acc[j], qa[kk], bf);
        }
    }

    const int r0 = row0 + warp * 16 + (lane >> 2);
    const int cb = 2 * (lane & 3);
#pragma unroll
    for (int j = 0; j < 16; j++) {
        const int c = c0 + 8 * j + cb;
        const float bx = bo[c], by = bo[c + 1];
        float2 w0 = make_float2(acc[j][0] + bx, acc[j][1] + by);
        float2 w1 = make_float2(acc[j][2] + bx, acc[j][3] + by);
        *(float2*)&out[(size_t)r0 * DMODEL + c]       = w0;
        *(float2*)&out[(size_t)(r0 + 8) * DMODEL + c] = w1;
    }
}

// ---------------------------------------------------------------------------
extern "C" void kernel_launch(void* const* d_in, const int* in_sizes, int n_in,
                              void* d_out, int out_size)
{
    const float* x  = (const float*)d_in[0];
    const float* Wq = (const float*)d_in[1];
    const float* bq = (const float*)d_in[2];
    const float* Wk = (const float*)d_in[3];
    const float* bk = (const float*)d_in[4];
    const float* Wv = (const float*)d_in[5];
    const float* bv = (const float*)d_in[6];
    const float* Wo = (const float*)d_in[7];
    const float* bo = (const float*)d_in[8];
    float* out = (float*)d_out;

    qkv_kernel<<<dim3(NROWS / 128, 3), 256>>>(x, Wq, bq, Wk, bk, Wv, bv);
    attn_kernel<<<256, 256>>>();
    combine_kernel<<<NROWS / 8, 256>>>();
    proj_kernel<<<dim3(NROWS / 128, DMODEL / 128), 256>>>(Wo, bo, out);
}

// round 15
// speedup vs baseline: 1.7673x; 1.1431x over previous
#include <cuda_runtime.h>
#include <cuda_fp16.h>
#include <math.h>
#include <cstdint>

// Fixed problem shapes: B=4, S=4096, D=512, H=64
#define BATCH 4
#define SEQ   4096
#define DMODEL 512
#define DHEAD  64
#define NROWS (BATCH*SEQ)          // 16384

// Scratch (device globals; no allocations allowed).
__device__ __half g_Qh[NROWS*DHEAD];   // fp16 Q row-major [row][h]
__device__ __half g_Kh[NROWS*DHEAD];   // fp16 K row-major
__device__ __half g_Vh[NROWS*DHEAD];   // fp16 V row-major
__device__ __half g_Oh[NROWS*DHEAD];   // fp16 combined attention output
// split-K partials (z = half index)
__device__ float  g_Op[2][NROWS*DHEAD];  // unnormalized O partials
__device__ float  g_m[2][NROWS];         // running max (base-2 domain)
__device__ float  g_l[2][NROWS];         // running sum

// ===========================================================================
// Warp-level MMA helpers (portable PTX — compute_103-safe)
// ===========================================================================
__device__ __forceinline__ uint32_t smem_u32(const void* p) {
    uint32_t a;
    asm("{ .reg .u64 t; cvta.to.shared.u64 t, %1; cvt.u32.u64 %0, t; }" : "=r"(a) : "l"(p));
    return a;
}
__device__ __forceinline__ void mma16816(float* d, const uint32_t* a, const uint32_t* b) {
    asm volatile(
        "mma.sync.aligned.m16n8k16.row.col.f32.f16.f16.f32 "
        "{%0,%1,%2,%3}, {%4,%5,%6,%7}, {%8,%9}, {%0,%1,%2,%3};"
        : "+f"(d[0]), "+f"(d[1]), "+f"(d[2]), "+f"(d[3])
        : "r"(a[0]), "r"(a[1]), "r"(a[2]), "r"(a[3]), "r"(b[0]), "r"(b[1]));
}
__device__ __forceinline__ void ldsm_x4(uint32_t* r, uint32_t addr) {
    asm volatile("ldmatrix.sync.aligned.m8n8.x4.shared.b16 {%0,%1,%2,%3}, [%4];"
        : "=r"(r[0]), "=r"(r[1]), "=r"(r[2]), "=r"(r[3]) : "r"(addr));
}
__device__ __forceinline__ void ldsm_x4t(uint32_t* r, uint32_t addr) {
    asm volatile("ldmatrix.sync.aligned.m8n8.x4.trans.shared.b16 {%0,%1,%2,%3}, [%4];"
        : "=r"(r[0]), "=r"(r[1]), "=r"(r[2]), "=r"(r[3]) : "r"(addr));
}
__device__ __forceinline__ void ldsm_x2t(uint32_t* r, uint32_t addr) {
    asm volatile("ldmatrix.sync.aligned.m8n8.x2.trans.shared.b16 {%0,%1}, [%2];"
        : "=r"(r[0]), "=r"(r[1]) : "r"(addr));
}
__device__ __forceinline__ float fast_exp2(float x) {
    float r;
    asm("ex2.approx.f32 %0, %1;" : "=f"(r) : "f"(x));
    return r;
}
__device__ __forceinline__ uint4 pack8(float4 a, float4 b) {
    __half2 h0 = __floats2half2_rn(a.x, a.y);
    __half2 h1 = __floats2half2_rn(a.z, a.w);
    __half2 h2 = __floats2half2_rn(b.x, b.y);
    __half2 h3 = __floats2half2_rn(b.z, b.w);
    uint4 u;
    u.x = *(uint32_t*)&h0; u.y = *(uint32_t*)&h1;
    u.z = *(uint32_t*)&h2; u.w = *(uint32_t*)&h3;
    return u;
}

// ===========================================================================
// Kernel 1: FUSED QKV projection via mma.sync fp16.
// One block = 128 rows x all three 64-col outputs (Q, K, V). x chunk is
// loaded ONCE per block (was 3x across separate blocks): x traffic 96->32 MB,
// and each chunk's LDG latency is amortized over 3x96 MMAs.
// Grid = 128 blocks (single wave on 148 SMs).
// ===========================================================================
__global__ __launch_bounds__(256) void qkv_kernel(
    const float* __restrict__ x,
    const float* __restrict__ Wq, const float* __restrict__ bq,
    const float* __restrict__ Wk, const float* __restrict__ bk,
    const float* __restrict__ Wv, const float* __restrict__ bv)
{
    __shared__ __align__(1024) __half Xs[128*64];      // 16 KB
    __shared__ __align__(1024) __half Wc[3][64*64];    // 24 KB

    const int tid  = threadIdx.x;
    const int lane = tid & 31;
    const int warp = tid >> 5;
    const int row0 = blockIdx.x * 128;

    const float* Wg[3] = {Wq, Wk, Wv};
    const float* bg[3] = {bq, bk, bv};
    __half* dst[3]     = {g_Qh, g_Kh, g_Vh};

    // ---- load chunk 0 (x + all three W chunks) ----
#pragma unroll
    for (int k = 0; k < 4; k++) {
        const int cid = tid + 256 * k;        // 0..1023
        const int r = cid >> 3, c = cid & 7;
        const float* src = &x[(size_t)(row0 + r) * DMODEL + c * 8];
        *(uint4*)&Xs[r * 64 + ((c ^ (r & 7)) * 8)] =
            pack8(*(const float4*)src, *(const float4*)(src + 4));
    }
#pragma unroll
    for (int g = 0; g < 3; g++) {
#pragma unroll
        for (int k = 0; k < 2; k++) {
            const int cid = tid + 256 * k;    // 0..511
            const int r = cid >> 3, c = cid & 7;
            const float* src = &Wg[g][(size_t)r * DHEAD + c * 8];
            *(uint4*)&Wc[g][r * 64 + ((c ^ (r & 7)) * 8)] =
                pack8(*(const float4*)src, *(const float4*)(src + 4));
        }
    }
    __syncthreads();

    const uint32_t xs_b = smem_u32(Xs);
    uint32_t wc_b[3];
#pragma unroll
    for (int g = 0; g < 3; g++) wc_b[g] = smem_u32(Wc[g]);

    const int rowl = warp * 16 + (lane & 15);
    const int hb   = lane >> 4;
    const int rl   = lane & 7;
    const uint32_t boff = (uint32_t)((lane & 15) * 128);

    float acc[3][8][4];
#pragma unroll
    for (int g = 0; g < 3; g++)
#pragma unroll
        for (int j = 0; j < 8; j++)
#pragma unroll
            for (int k = 0; k < 4; k++) acc[g][j][k] = 0.0f;

    for (int dc8 = 0; dc8 < 8; dc8++) {
        const bool has = (dc8 + 1) < 8;
        uint4 xpre[4], wpre[3][2];
        if (has) {
            const int dc = (dc8 + 1) * 64;
#pragma unroll
            for (int k = 0; k < 4; k++) {
                const int cid = tid + 256 * k;
                const int r = cid >> 3, c = cid & 7;
                const float* src = &x[(size_t)(row0 + r) * DMODEL + dc + c * 8];
                xpre[k] = pack8(*(const float4*)src, *(const float4*)(src + 4));
            }
#pragma unroll
            for (int g = 0; g < 3; g++) {
#pragma unroll
                for (int k = 0; k < 2; k++) {
                    const int cid = tid + 256 * k;
                    const int r = cid >> 3, c = cid & 7;
                    const float* src = &Wg[g][(size_t)(dc + r) * DHEAD + c * 8];
                    wpre[g][k] = pack8(*(const float4*)src, *(const float4*)(src + 4));
                }
            }
        }

        uint32_t qa[4][4];
#pragma unroll
        for (int kk = 0; kk < 4; kk++)
            ldsm_x4(qa[kk], xs_b + rowl * 128 + (((2 * kk + hb) ^ (rowl & 7)) * 16));

#pragma unroll
        for (int g = 0; g < 3; g++) {
#pragma unroll
            for (int j = 0; j < 8; j++) {
#pragma unroll
                for (int kk = 0; kk < 4; kk++) {
                    uint32_t bf[2];
                    ldsm_x2t(bf, wc_b[g] + (uint32_t)(kk * 2048) + boff
                                 + (uint32_t)(((j ^ rl) * 16)));
                    mma16816(acc[g][j], qa[kk], bf);
                }
            }
        }

        if (has) {
            __syncthreads();
#pragma unroll
            for (int k = 0; k < 4; k++) {
                const int cid = tid + 256 * k;
                const int r = cid >> 3, c = cid & 7;
                *(uint4*)&Xs[r * 64 + ((c ^ (r & 7)) * 8)] = xpre[k];
            }
#pragma unroll
            for (int g = 0; g < 3; g++) {
#pragma unroll
                for (int k = 0; k < 2; k++) {
                    const int cid = tid + 256 * k;
                    const int r = cid >> 3, c = cid & 7;
                    *(uint4*)&Wc[g][r * 64 + ((c ^ (r & 7)) * 8)] = wpre[g][k];
                }
            }
            __syncthreads();
        }
    }

    // ---- epilogue: + bias, fp16 store (all three outputs) ----
    const int r0 = row0 + warp * 16 + (lane >> 2);
    const int cb = 2 * (lane & 3);
#pragma unroll
    for (int g = 0; g < 3; g++) {
#pragma unroll
        for (int j = 0; j < 8; j++) {
            const int c = 8 * j + cb;
            const float bx = bg[g][c], by = bg[g][c + 1];
            __half2 h0 = __floats2half2_rn(acc[g][j][0] + bx, acc[g][j][1] + by);
            __half2 h1 = __floats2half2_rn(acc[g][j][2] + bx, acc[g][j][3] + by);
            *(__half2*)&dst[g][(size_t)r0 * DHEAD + c]       = h0;
            *(__half2*)&dst[g][(size_t)(r0 + 8) * DHEAD + c] = h1;
        }
    }
}

// ===========================================================================
// Kernel 2: split-K fp16 mma.sync flash attention (UNCHANGED from R13 win).
// NOTE: no occupancy hint — (256,2) capped regs at 128 and spilled (R12).
// ===========================================================================
__global__ __launch_bounds__(256) void attn_kernel()
{
    __shared__ __align__(1024) __half Qs[128*64];
    __shared__ __align__(1024) __half Ks[64*64];
    __shared__ __align__(1024) __half Vs[64*64];

    const int tid  = threadIdx.x;
    const int lane = tid & 31;
    const int warp = tid >> 5;

    // rank map: heaviest ranks -> singles; pair sums ~constant
    const int bid = blockIdx.x;
    const int rank = (bid < 108) ? (40 + bid) : (bid < 148) ? (bid - 108) : (403 - bid);
    const int qt = 31 - (rank >> 3);   // 0..31
    const int sub = rank & 7;
    const int b = sub & 3;             // batch
    const int z = sub >> 2;            // key-half
    const int qbase = qt * 128;
    const int kb_lo = z * (qt + 1);
    const int kb_hi = kb_lo + (qt + 1);

    // load Q tile + first K/V tile
    const __half* Qg = g_Qh + ((size_t)b * SEQ + qbase) * DHEAD;
    for (int i = tid; i < 1024; i += 256) {
        const int r = i >> 3, c = i & 7;
        *(uint4*)&Qs[r * 64 + ((c ^ (r & 7)) * 8)] = *(const uint4*)&Qg[(size_t)r * 64 + c * 8];
    }
    {
        const __half* Kg = g_Kh + ((size_t)b * SEQ + kb_lo * 64) * DHEAD;
        const __half* Vg = g_Vh + ((size_t)b * SEQ + kb_lo * 64) * DHEAD;
        for (int i = tid; i < 512; i += 256) {
            const int r = i >> 3, c = i & 7;
            *(uint4*)&Ks[r * 64 + ((c ^ (r & 7)) * 8)] = *(const uint4*)&Kg[(size_t)r * 64 + c * 8];
            *(uint4*)&Vs[r * 64 + ((c ^ (r & 7)) * 8)] = *(const uint4*)&Vg[(size_t)r * 64 + c * 8];
        }
    }
    __syncthreads();

    const uint32_t qs_b = smem_u32(Qs);
    const uint32_t ks_b = smem_u32(Ks);
    const uint32_t vs_b = smem_u32(Vs);

    // persistent Q A-fragments
    const int q0 = warp * 16;
    uint32_t qa[4][4];
    {
        const int rowl = q0 + (lane & 15);
        const int hb = lane >> 4;
#pragma unroll
        for (int kk = 0; kk < 4; kk++)
            ldsm_x4(qa[kk], qs_b + rowl * 128 + (((2 * kk + hb) ^ (rowl & 7)) * 16));
    }

    const int rl  = lane & 7;
    const int hb8 = (lane >> 3) & 1;
    const int krow_off = ((lane & 16) >> 1) + rl;   // 0..15
    uint32_t koff2[4];
#pragma unroll
    for (int kk = 0; kk < 4; kk++)
        koff2[kk] = (uint32_t)(krow_off * 128 + (((2 * kk + hb8) ^ rl) * 16));
    const uint32_t voff = (uint32_t)((lane & 15) * 128);
    const int hv = lane >> 4;

    const int row0 = qbase + q0 + (lane >> 2);
    const float C = 0.015625f * 1.44269504088896f; // (1/sqrt(4096)) * log2(e)

    float m0 = -1e30f, m1 = -1e30f, l0 = 0.0f, l1 = 0.0f;
    float o[8][4];
#pragma unroll
    for (int j = 0; j < 8; j++)
#pragma unroll
        for (int k = 0; k < 4; k++) o[j][k] = 0.0f;

    for (int kb = kb_lo; kb < kb_hi; kb++) {
        // prefetch next K/V tile into registers
        const bool has = (kb + 1) < kb_hi;
        uint4 kpre[2], vpre[2];
        if (has) {
            const __half* Kg = g_Kh + ((size_t)b * SEQ + (kb + 1) * 64) * DHEAD;
            const __half* Vg = g_Vh + ((size_t)b * SEQ + (kb + 1) * 64) * DHEAD;
#pragma unroll
            for (int t = 0; t < 2; t++) {
                const int i = tid + 256 * t;
                const int r = i >> 3, c = i & 7;
                kpre[t] = *(const uint4*)&Kg[(size_t)r * 64 + c * 8];
                vpre[t] = *(const uint4*)&Vg[(size_t)r * 64 + c * 8];
            }
        }

        // ---- S = Q * K^T (x4 ldsm: two j per load) ----
        float s[8][4];
#pragma unroll
        for (int j = 0; j < 8; j++)
#pragma unroll
            for (int k = 0; k < 4; k++) s[j][k] = 0.0f;

#pragma unroll
        for (int j = 0; j < 8; j += 2) {
#pragma unroll
            for (int kk = 0; kk < 4; kk++) {
                uint32_t bf[4];
                ldsm_x4(bf, ks_b + (uint32_t)(j * 1024) + koff2[kk]);
                mma16816(s[j],     qa[kk], bf);
                mma16816(s[j + 1], qa[kk], bf + 2);
            }
        }

        // ---- scale (+ causal mask on diagonal tiles) ----
#pragma unroll
        for (int j = 0; j < 8; j++)
#pragma unroll
            for (int k = 0; k < 4; k++) s[j][k] *= C;

        if (kb * 64 + 63 > qbase + q0) {
#pragma unroll
            for (int j = 0; j < 8; j++) {
                const int kc = kb * 64 + 8 * j + 2 * (lane & 3);
                if (kc     > row0)     s[j][0] = -1e30f;
                if (kc + 1 > row0)     s[j][1] = -1e30f;
                if (kc     > row0 + 8) s[j][2] = -1e30f;
                if (kc + 1 > row0 + 8) s[j][3] = -1e30f;
            }
        }

        // ---- online softmax ----
        float mx0 = -1e30f, mx1 = -1e30f;
#pragma unroll
        for (int j = 0; j < 8; j++) {
            mx0 = fmaxf(mx0, fmaxf(s[j][0], s[j][1]));
            mx1 = fmaxf(mx1, fmaxf(s[j][2], s[j][3]));
        }
        mx0 = fmaxf(mx0, __shfl_xor_sync(0xffffffffu, mx0, 1, 4));
        mx0 = fmaxf(mx0, __shfl_xor_sync(0xffffffffu, mx0, 2, 4));
        mx1 = fmaxf(mx1, __shfl_xor_sync(0xffffffffu, mx1, 1, 4));
        mx1 = fmaxf(mx1, __shfl_xor_sync(0xffffffffu, mx1, 2, 4));

        const float mn0 = fmaxf(m0, mx0);
        const float mn1 = fmaxf(m1, mx1);
        const float c0 = fast_exp2(m0 - mn0);
        const float c1 = fast_exp2(m1 - mn1);
        m0 = mn0; m1 = mn1;

        uint32_t pa[4][4];
        float sum0 = 0.0f, sum1 = 0.0f;
#pragma unroll
        for (int j = 0; j < 8; j++) {
            const float p0 = fast_exp2(s[j][0] - mn0);
            const float p1 = fast_exp2(s[j][1] - mn0);
            const float p2 = fast_exp2(s[j][2] - mn1);
            const float p3 = fast_exp2(s[j][3] - mn1);
            sum0 += p0 + p1;
            sum1 += p2 + p3;
            const __half2 h01 = __floats2half2_rn(p0, p1);
            const __half2 h23 = __floats2half2_rn(p2, p3);
            const int kk = j >> 1, hi = (j & 1) << 1;
            pa[kk][hi]     = *(const uint32_t*)&h01;
            pa[kk][hi + 1] = *(const uint32_t*)&h23;
        }
        sum0 += __shfl_xor_sync(0xffffffffu, sum0, 1, 4);
        sum0 += __shfl_xor_sync(0xffffffffu, sum0, 2, 4);
        sum1 += __shfl_xor_sync(0xffffffffu, sum1, 1, 4);
        sum1 += __shfl_xor_sync(0xffffffffu, sum1, 2, 4);
        l0 = l0 * c0 + sum0;
        l1 = l1 * c1 + sum1;

#pragma unroll
        for (int j = 0; j < 8; j++) {
            o[j][0] *= c0; o[j][1] *= c0;
            o[j][2] *= c1; o[j][3] *= c1;
        }

        // ---- O += P * V (x4 trans ldsm: two j per load) ----
#pragma unroll
        for (int kk = 0; kk < 4; kk++) {
#pragma unroll
            for (int j = 0; j < 8; j += 2) {
                uint32_t vb[4];
                ldsm_x4t(vb, vs_b + (uint32_t)(kk * 2048) + voff
                             + (uint32_t)((((j + hv) ^ rl) * 16)));
                mma16816(o[j],     pa[kk], vb);
                mma16816(o[j + 1], pa[kk], vb + 2);
            }
        }

        if (has) {
            __syncthreads();
#pragma unroll
            for (int t = 0; t < 2; t++) {
                const int i = tid + 256 * t;
                const int r = i >> 3, c = i & 7;
                *(uint4*)&Ks[r * 64 + ((c ^ (r & 7)) * 8)] = kpre[t];
                *(uint4*)&Vs[r * 64 + ((c ^ (r & 7)) * 8)] = vpre[t];
            }
            __syncthreads();
        }
    }

    // ---- epilogue: unnormalized partials (fp32) + m/l ----
    float* Op0 = &g_Op[z][((size_t)b * SEQ + row0) * DHEAD];
    float* Op1 = Op0 + 8 * DHEAD;
    const int cbase = 2 * (lane & 3);
#pragma unroll
    for (int j = 0; j < 8; j++) {
        *(float2*)&Op0[8 * j + cbase] = make_float2(o[j][0], o[j][1]);
        *(float2*)&Op1[8 * j + cbase] = make_float2(o[j][2], o[j][3]);
    }
    if ((lane & 3) == 0) {
        const size_t gr = (size_t)b * SEQ + row0;
        g_m[z][gr] = m0;  g_l[z][gr] = l0;
        g_m[z][gr + 8] = m1;  g_l[z][gr + 8] = l1;
    }
}

// ===========================================================================
// Kernel 2b: combine the two split-K halves -> fp16 g_Oh (unchanged).
// ===========================================================================
__global__ __launch_bounds__(256) void combine_kernel()
{
    const int tid  = threadIdx.x;
    const int lane = tid & 31;
    const int warp = tid >> 5;
    const int row  = blockIdx.x * 8 + warp;

    const float m0 = g_m[0][row], m1 = g_m[1][row];
    const float l0 = g_l[0][row], l1 = g_l[1][row];
    const float mm = fmaxf(m0, m1);
    const float a0 = fast_exp2(m0 - mm);
    const float a1 = fast_exp2(m1 - mm);
    const float inv = 1.0f / (l0 * a0 + l1 * a1);
    const float w0 = a0 * inv, w1 = a1 * inv;

    const float2 v0 = *(const float2*)&g_Op[0][(size_t)row * DHEAD + 2 * lane];
    const float2 v1 = *(const float2*)&g_Op[1][(size_t)row * DHEAD + 2 * lane];
    __half2 h = __floats2half2_rn(v0.x * w0 + v1.x * w1, v0.y * w0 + v1.y * w1);
    *(__half2*)&g_Oh[(size_t)row * DHEAD + 2 * lane] = h;
}

// ===========================================================================
// Kernel 3: output projection via mma.sync fp16 (unchanged — measured 15 µs).
// ===========================================================================
__global__ __launch_bounds__(256) void proj_kernel(
    const float* __restrict__ Wo, const float* __restrict__ bo,
    float* __restrict__ out)
{
    __shared__ __align__(1024) __half Os[128*64];
    __shared__ __align__(1024) __half Wc0[64*64];
    __shared__ __align__(1024) __half Wc1[64*64];

    const int tid  = threadIdx.x;
    const int lane = tid & 31;
    const int warp = tid >> 5;
    const int row0 = blockIdx.x * 128;
    const int c0   = blockIdx.y * 128;

    for (int i = tid; i < 1024; i += 256) {
        const int r = i >> 3, c = i & 7;
        *(uint4*)&Os[r * 64 + ((c ^ (r & 7)) * 8)] =
            *(const uint4*)&g_Oh[(size_t)(row0 + r) * DHEAD + c * 8];
    }
    for (int i = tid; i < 1024; i += 256) {
        const int h = i >> 4, c = i & 15;
        const float* src = &Wo[(size_t)h * DMODEL + c0 + c * 8];
        uint4 u = pack8(*(const float4*)src, *(const float4*)(src + 4));
        __half* dst = (c < 8) ? Wc0 : Wc1;
        const int cc = c & 7;
        *(uint4*)&dst[h * 64 + ((cc ^ (h & 7)) * 8)] = u;
    }
    __syncthreads();

    const uint32_t os_b  = smem_u32(Os);
    const uint32_t wc0_b = smem_u32(Wc0);
    const uint32_t wc1_b = smem_u32(Wc1);

    const int rowl = warp * 16 + (lane & 15);
    const int hb = lane >> 4;
    uint32_t qa[4][4];
#pragma unroll
    for (int kk = 0; kk < 4; kk++)
        ldsm_x4(qa[kk], os_b + rowl * 128 + (((2 * kk + hb) ^ (rowl & 7)) * 16));

    const int rl = lane & 7;
    const uint32_t boff = (uint32_t)((lane & 15) * 128);

    float acc[16][4];
#pragma unroll
    for (int j = 0; j < 16; j++)
#pragma unroll
        for (int k = 0; k < 4; k++) acc[j][k] = 0.0f;

#pragma unroll
    for (int j = 0; j < 16; j++) {
        const uint32_t base = (j < 8) ? wc0_b : wc1_b;
        const int jj = j & 7;
#pragma unroll
        for (int kk = 0; kk < 4; kk++) {
            uint32_t bf[2];
            ldsm_x2t(bf, base + (uint32_t)(kk * 2048) + boff + (uint32_t)(((jj ^ rl) * 16)));
            mma16816(acc[j], qa[kk], bf);
        }
    }

    const int r0 = row0 + warp * 16 + (lane >> 2);
    const int cb = 2 * (lane & 3);
#pragma unroll
    for (int j = 0; j < 16; j++) {
        const int c = c0 + 8 * j + cb;
        const float bx = bo[c], by = bo[c + 1];
        float2 w0 = make_float2(acc[j][0] + bx, acc[j][1] + by);
        float2 w1 = make_float2(acc[j][2] + bx, acc[j][3] + by);
        *(float2*)&out[(size_t)r0 * DMODEL + c]       = w0;
        *(float2*)&out[(size_t)(r0 + 8) * DMODEL + c] = w1;
    }
}

// ---------------------------------------------------------------------------
extern "C" void kernel_launch(void* const* d_in, const int* in_sizes, int n_in,
                              void* d_out, int out_size)
{
    const float* x  = (const float*)d_in[0];
    const float* Wq = (const float*)d_in[1];
    const float* bq = (const float*)d_in[2];
    const float* Wk = (const float*)d_in[3];
    const float* bk = (const float*)d_in[4];
    const float* Wv = (const float*)d_in[5];
    const float* bv = (const float*)d_in[6];
    const float* Wo = (const float*)d_in[7];
    const float* bo = (const float*)d_in[8];
    float* out = (float*)d_out;

    qkv_kernel<<<NROWS / 128, 256>>>(x, Wq, bq, Wk, bk, Wv, bv);
    attn_kernel<<<256, 256>>>();
    combine_kernel<<<NROWS / 8, 256>>>();
    proj_kernel<<<dim3(NROWS / 128, DMODEL / 128), 256>>>(Wo, bo, out);
}